// round 6
// baseline (speedup 1.0000x reference)
#include <cuda_runtime.h>
#include <cuda_bf16.h>
#include <cstdint>

// Problem constants
#define DIMD 512
#define KCB  1024
#define TT   2048
#define BBATCH 16
#define NROWS (BBATCH * TT)          // 32768
#define TOTAL (BBATCH * DIMD * TT)   // 16777216
#define KTOT  1536                   // [hi | lo | hi] x [hi | hi | lo]

#define EPS_CERT 4e-4f

// Scratch (no cudaMalloc allowed)
__device__ float  g_wsq[KCB];
__device__ float  g_zsq[NROWS];
__device__ int    g_idx[NROWS];
__device__ unsigned char g_flag[NROWS];
__device__ int    g_list[NROWS];
__device__ int    g_nflag;
__device__ double g_loss_acc;
__device__ __nv_bfloat16 g_A[(size_t)NROWS * KTOT];   // ~100MB
__device__ __nv_bfloat16 g_B[(size_t)KCB * KTOT];     // 3MB

// ---------------------------------------------------------------------------
// Helpers (all base-target PTX: sm_80-era, accepted by ptxas for sm_103)
// ---------------------------------------------------------------------------
__device__ __forceinline__ uint32_t smem_u32(const void* p) {
    uint32_t a;
    asm("{ .reg .u64 t; cvta.to.shared.u64 t, %1; cvt.u32.u64 %0, t; }"
        : "=r"(a) : "l"(p));
    return a;
}
#define CP_ASYNC16(dst, src) \
    asm volatile("cp.async.cg.shared.global [%0], [%1], 16;" \
                 :: "r"(dst), "l"(src))
#define CP_COMMIT() asm volatile("cp.async.commit_group;")
#define CP_WAIT(n)  asm volatile("cp.async.wait_group %0;" :: "n"(n))

__device__ __forceinline__ void ldmx4(uint32_t* r, uint32_t addr) {
    asm volatile("ldmatrix.sync.aligned.m8n8.x4.shared.b16 {%0,%1,%2,%3}, [%4];"
                 : "=r"(r[0]), "=r"(r[1]), "=r"(r[2]), "=r"(r[3]) : "r"(addr));
}
__device__ __forceinline__ void mma16816(float* c, const uint32_t* a,
                                         const uint32_t* b) {
    asm volatile(
        "mma.sync.aligned.m16n8k16.row.col.f32.bf16.bf16.f32 "
        "{%0,%1,%2,%3}, {%4,%5,%6,%7}, {%8,%9}, {%0,%1,%2,%3};"
        : "+f"(c[0]), "+f"(c[1]), "+f"(c[2]), "+f"(c[3])
        : "r"(a[0]), "r"(a[1]), "r"(a[2]), "r"(a[3]), "r"(b[0]), "r"(b[1]));
}
#define SWZ(x) ((x) ^ (((x) >> 3) & 0x70))

// ---------------------------------------------------------------------------
__global__ void vq_init_kernel() { g_loss_acc = 0.0; g_nflag = 0; }

// ---------------------------------------------------------------------------
// z_sq (bitwise: scalar sequential over d, unfused mul/add) — validated R2
// ---------------------------------------------------------------------------
__global__ __launch_bounds__(256)
void vq_zsq_kernel(const float* __restrict__ z) {
    int n = blockIdx.x * blockDim.x + threadIdx.x;
    if (n >= NROWS) return;
    int b = n >> 11;
    int t = n & (TT - 1);
    const float* p = z + ((size_t)b << 20) + t;
    float s = 0.f;
    #pragma unroll 8
    for (int d = 0; d < DIMD; ++d) {
        float v = p[(size_t)d * TT];
        s = __fadd_rn(s, __fmul_rn(v, v));
    }
    g_zsq[n] = s;
}

// ---------------------------------------------------------------------------
// w_sq (validated R2)
// ---------------------------------------------------------------------------
__global__ __launch_bounds__(256)
void vq_wsq_kernel(const float* __restrict__ cb) {
    int k = blockIdx.x * blockDim.x + threadIdx.x;
    if (k >= KCB) return;
    const float* row = cb + (size_t)k * DIMD;
    float s = 0.f;
    #pragma unroll 8
    for (int d = 0; d < DIMD; ++d)
        s = __fadd_rn(s, __fmul_rn(row[d], row[d]));
    g_wsq[k] = s;
}

// ---------------------------------------------------------------------------
// Codebook split into concat layout: B[k] = [hi(512) | hi(512) | lo(512)]
// ---------------------------------------------------------------------------
__global__ __launch_bounds__(256)
void vq_prep_cb_kernel(const float* __restrict__ cb) {
    int i = blockIdx.x * blockDim.x + threadIdx.x;
    if (i >= KCB * DIMD) return;
    int k = i >> 9, d = i & 511;
    float v = cb[i];
    __nv_bfloat16 hi = __float2bfloat16(v);
    __nv_bfloat16 lo = __float2bfloat16(__fsub_rn(v, __bfloat162float(hi)));
    size_t base = (size_t)k * KTOT;
    g_B[base + d]        = hi;
    g_B[base + 512 + d]  = hi;
    g_B[base + 1024 + d] = lo;
}

// ---------------------------------------------------------------------------
// z transpose + split: A[n] = [hi(512) | lo(512) | hi(512)]
// ---------------------------------------------------------------------------
__global__ __launch_bounds__(256)
void vq_prep_z_kernel(const float* __restrict__ z) {
    __shared__ float tile[32][33];
    int b  = blockIdx.z;
    int t0 = blockIdx.x * 32;
    int d0 = blockIdx.y * 32;
    int tx = threadIdx.x, ty = threadIdx.y;
    #pragma unroll
    for (int i = 0; i < 4; ++i) {
        int d = d0 + ty + i * 8;
        tile[ty + i * 8][tx] = z[((size_t)b * DIMD + d) * TT + t0 + tx];
    }
    __syncthreads();
    #pragma unroll
    for (int i = 0; i < 4; ++i) {
        int tl = ty + i * 8;
        int n  = b * TT + t0 + tl;
        float v = tile[tx][tl];
        __nv_bfloat16 hi = __float2bfloat16(v);
        __nv_bfloat16 lo = __float2bfloat16(__fsub_rn(v, __bfloat162float(hi)));
        size_t base = (size_t)n * KTOT;
        int d = d0 + tx;
        g_A[base + d]        = hi;
        g_A[base + 512 + d]  = lo;
        g_A[base + 1024 + d] = hi;
    }
}

// ---------------------------------------------------------------------------
// Main HMMA kernel: CTA = 128 rows x (8 panels of 128 codes), K = 1536.
// 8 warps as 4(M) x 2(N): warp tile 32x64. cp.async double-buffered 64-wide
// k-chunks, ldmatrix x4 fragments, fp32 accumulators = dot3.
// Epilogue per panel: v = wsq - 2*dot3, per-thread running top-2 per row.
// ---------------------------------------------------------------------------
#define OFF_A    0
#define OFF_B    32768
#define OFF_WSQ  65536
#define OFF_REDM 66048
#define OFF_REDI 68096
#define GEMM_SMEM 69120

__global__ __launch_bounds__(256)
void vq_mma_kernel(float* __restrict__ out_idx_f) {
    extern __shared__ char smem[];
    const uint32_t sb = smem_u32(smem);
    float*  wsq_s = (float*)(smem + OFF_WSQ);
    float2* red_m = (float2*)(smem + OFF_REDM);  // [2][128]
    int*    red_i = (int*)(smem + OFF_REDI);     // [2][128]

    const int tid  = threadIdx.x;
    const int wid  = tid >> 5;
    const int lane = tid & 31;
    const int rb   = blockIdx.x * 128;
    const int warp_m = (wid >> 1) * 32;
    const int warp_n = (wid & 1) * 64;

    // ldmatrix per-lane geometry (canonical m16n8k16 mapping)
    const int a_row   = warp_m + (lane & 7) + ((lane >> 3) & 1) * 8;
    const int a_half  = ((lane >> 4) & 1) * 16;
    const int b_row   = warp_n + (lane & 7) + ((lane >> 4) & 1) * 8;
    const int b_half  = ((lane >> 3) & 1) * 16;

    float m1[4] = {1e30f, 1e30f, 1e30f, 1e30f};
    float m2[4] = {1e30f, 1e30f, 1e30f, 1e30f};
    int   i1[4] = {0, 0, 0, 0};

    for (int panel = 0; panel < 8; ++panel) {
        __syncthreads();                       // smem reuse guard
        if (tid < 128) wsq_s[tid] = g_wsq[panel * 128 + tid];

        float acc[2][8][4];
        #pragma unroll
        for (int mi = 0; mi < 2; ++mi)
            #pragma unroll
            for (int f = 0; f < 8; ++f)
                #pragma unroll
                for (int q = 0; q < 4; ++q) acc[mi][f][q] = 0.f;

        // ---- prologue: chunk 0 into stage 0
        {
            #pragma unroll
            for (int i = 0; i < 4; ++i) {
                int e = tid + i * 256;
                int row = e >> 3, col = e & 7;
                uint32_t dst = sb + OFF_A + SWZ((uint32_t)(row * 128 + col * 16));
                CP_ASYNC16(dst, &g_A[(size_t)(rb + row) * KTOT + col * 8]);
            }
            #pragma unroll
            for (int i = 0; i < 4; ++i) {
                int e = tid + i * 256;
                int row = e >> 3, col = e & 7;
                uint32_t dst = sb + OFF_B + SWZ((uint32_t)(row * 128 + col * 16));
                CP_ASYNC16(dst, &g_B[(size_t)(panel * 128 + row) * KTOT + col * 8]);
            }
            CP_COMMIT();
        }

        for (int c = 0; c < 24; ++c) {
            if (c < 23) {
                const int nc = c + 1;
                const uint32_t stn = (uint32_t)(nc & 1) * 16384u;
                #pragma unroll
                for (int i = 0; i < 4; ++i) {
                    int e = tid + i * 256;
                    int row = e >> 3, col = e & 7;
                    uint32_t dst = sb + OFF_A + stn + SWZ((uint32_t)(row * 128 + col * 16));
                    CP_ASYNC16(dst, &g_A[(size_t)(rb + row) * KTOT + nc * 64 + col * 8]);
                }
                #pragma unroll
                for (int i = 0; i < 4; ++i) {
                    int e = tid + i * 256;
                    int row = e >> 3, col = e & 7;
                    uint32_t dst = sb + OFF_B + stn + SWZ((uint32_t)(row * 128 + col * 16));
                    CP_ASYNC16(dst, &g_B[(size_t)(panel * 128 + row) * KTOT + nc * 64 + col * 8]);
                }
                CP_COMMIT();
                CP_WAIT(1);
            } else {
                CP_WAIT(0);
            }
            __syncthreads();

            const uint32_t aB = sb + OFF_A + (uint32_t)(c & 1) * 16384u;
            const uint32_t bB = sb + OFF_B + (uint32_t)(c & 1) * 16384u;
            #pragma unroll
            for (int kk = 0; kk < 4; ++kk) {
                uint32_t af[2][4];
                #pragma unroll
                for (int mi = 0; mi < 2; ++mi)
                    ldmx4(af[mi], aB + SWZ((uint32_t)(((a_row + mi * 16) << 7) + kk * 32 + a_half)));
                #pragma unroll
                for (int j = 0; j < 4; ++j) {
                    uint32_t bf[4];
                    ldmx4(bf, bB + SWZ((uint32_t)(((b_row + j * 16) << 7) + kk * 32 + b_half)));
                    mma16816(acc[0][2 * j],     af[0], bf);
                    mma16816(acc[0][2 * j + 1], af[0], bf + 2);
                    mma16816(acc[1][2 * j],     af[1], bf);
                    mma16816(acc[1][2 * j + 1], af[1], bf + 2);
                }
            }
            __syncthreads();   // compute done before next loads overwrite
        }

        // ---- epilogue: running per-row top-2
        #pragma unroll
        for (int mi = 0; mi < 2; ++mi) {
            #pragma unroll
            for (int f = 0; f < 8; ++f) {
                int cbase = warp_n + f * 8 + (lane & 3) * 2;
                float w0 = wsq_s[cbase], w1 = wsq_s[cbase + 1];
                int gi = panel * 128 + cbase;
                #pragma unroll
                for (int half = 0; half < 2; ++half) {
                    int s = mi * 2 + half;
                    float v0 = __fmaf_rn(-2.0f, acc[mi][f][half * 2],     w0);
                    float v1 = __fmaf_rn(-2.0f, acc[mi][f][half * 2 + 1], w1);
                    if (v0 < m1[s]) { m2[s] = m1[s]; m1[s] = v0; i1[s] = gi; }
                    else if (v0 < m2[s]) m2[s] = v0;
                    if (v1 < m1[s]) { m2[s] = m1[s]; m1[s] = v1; i1[s] = gi + 1; }
                    else if (v1 < m2[s]) m2[s] = v1;
                }
            }
        }
    }

    // ---- cross-lane (quad) reduce, then cross-warp via smem
    #pragma unroll
    for (int s = 0; s < 4; ++s) {
        float a1 = m1[s], a2 = m2[s];
        int   ai = i1[s];
        #pragma unroll
        for (int off = 1; off <= 2; off <<= 1) {
            float o1 = __shfl_xor_sync(0xffffffffu, a1, off);
            int   oi = __shfl_xor_sync(0xffffffffu, ai, off);
            float o2 = __shfl_xor_sync(0xffffffffu, a2, off);
            if (o1 < a1 || (o1 == a1 && oi < ai)) {
                a2 = fminf(a1, o2); a1 = o1; ai = oi;
            } else {
                a2 = fminf(a2, o1);
            }
        }
        if ((lane & 3) == 0) {
            int rl = warp_m + (lane >> 2) + s * 8;
            red_m[(wid & 1) * 128 + rl] = make_float2(a1, a2);
            red_i[(wid & 1) * 128 + rl] = ai;
        }
    }
    __syncthreads();
    if (tid < 128) {
        float2 pa = red_m[tid];
        float2 pb = red_m[128 + tid];
        int ia = red_i[tid], ib = red_i[128 + tid];
        float a1, a2; int ai;
        if (pb.x < pa.x || (pb.x == pa.x && ib < ia)) {
            a1 = pb.x; ai = ib; a2 = fminf(pa.x, pb.y);
        } else {
            a1 = pa.x; ai = ia; a2 = fminf(pa.y, pb.x);
        }
        int n = rb + tid;
        g_idx[n]     = ai;
        out_idx_f[n] = (float)ai;
        g_flag[n]    = (a2 - a1 <= EPS_CERT) ? 1 : 0;
    }
}

// ---------------------------------------------------------------------------
// Compact flagged rows into g_list (order nondeterministic; results aren't)
// ---------------------------------------------------------------------------
__global__ __launch_bounds__(256)
void vq_compact_kernel() {
    int n = blockIdx.x * blockDim.x + threadIdx.x;
    if (n < NROWS && g_flag[n]) {
        int p = atomicAdd(&g_nflag, 1);
        g_list[p] = n;
    }
}

// ---------------------------------------------------------------------------
// Rescue: blocks of 8 flagged rows share smem-staged codebook tiles.
// Bitwise pipeline: serial fmaf chain ascending d, fl(fl(zsq-2dot)+wsq),
// lowest-index tie-break. Codebook traffic: ~2MB per 8 rows.
// ---------------------------------------------------------------------------
#define RS_ZS   0                       // 8 x 512 floats = 16384B
#define RS_CB   16384                   // 32 x 513 floats = 65664B
#define RS_SMEM (16384 + 65664)

__global__ __launch_bounds__(256)
void vq_rescue_kernel(const float* __restrict__ z,
                      const float* __restrict__ cb,
                      float* __restrict__ out_idx_f) {
    extern __shared__ char smem[];
    float* zs  = (float*)(smem + RS_ZS);    // [8][512]
    float* cbs = (float*)(smem + RS_CB);    // [32][513]
    const int tid  = threadIdx.x;
    const int wid  = tid >> 5;
    const int lane = tid & 31;
    const int nflag = g_nflag;

    for (int base = blockIdx.x * 8; base < nflag; base += gridDim.x * 8) {
        const bool valid = (base + wid) < nflag;
        int nrow = 0;
        float zsq = 0.f;
        if (valid) {
            nrow = g_list[base + wid];
            int b = nrow >> 11, t = nrow & (TT - 1);
            const float* zp = z + ((size_t)b << 20) + t;
            for (int d = lane; d < DIMD; d += 32)
                zs[wid * 512 + d] = zp[(size_t)d * TT];
            zsq = g_zsq[nrow];
        }

        float bv = 1e30f;
        int   bi = 0;
        for (int chunk = 0; chunk < 32; ++chunk) {
            __syncthreads();
            for (int i = tid; i < 32 * 512; i += 256) {
                int code = i >> 9, d = i & 511;
                cbs[code * 513 + d] = cb[(size_t)(chunk * 32 + code) * DIMD + d];
            }
            __syncthreads();
            if (valid) {
                const float* crow = &cbs[lane * 513];
                const float* zrow = &zs[wid * 512];
                float acc = 0.f;
                #pragma unroll 8
                for (int d = 0; d < DIMD; ++d)
                    acc = __fmaf_rn(zrow[d], crow[d], acc);
                int k = chunk * 32 + lane;
                float tt = __fsub_rn(zsq, __fmul_rn(2.0f, acc));
                float dv = __fadd_rn(tt, g_wsq[k]);
                if (dv < bv) { bv = dv; bi = k; }   // ascending k -> first min
            }
        }
        #pragma unroll
        for (int off = 16; off; off >>= 1) {
            float ov = __shfl_xor_sync(0xffffffffu, bv, off);
            int   oi = __shfl_xor_sync(0xffffffffu, bi, off);
            if (ov < bv || (ov == bv && oi < bi)) { bv = ov; bi = oi; }
        }
        if (valid && lane == 0) {
            g_idx[nrow]     = bi;
            out_idx_f[nrow] = (float)bi;
        }
    }
}

// ---------------------------------------------------------------------------
// Gather z_q, write z_q_st, accumulate loss (validated R2)
// ---------------------------------------------------------------------------
__global__ __launch_bounds__(256)
void vq_gather_kernel(const float* __restrict__ z,
                      const float* __restrict__ cb,
                      float* __restrict__ out) {
    float ls = 0.f;
    const int stride = gridDim.x * blockDim.x;
    for (int o = blockIdx.x * blockDim.x + threadIdx.x; o < TOTAL; o += stride) {
        int t = o & (TT - 1);
        int d = (o >> 11) & (DIMD - 1);
        int b = o >> 20;
        int n = (b << 11) + t;
        int idx = g_idx[n];
        float w  = __ldg(cb + (size_t)idx * DIMD + d);
        float zv = z[o];
        float diff = __fsub_rn(w, zv);
        out[o] = __fadd_rn(zv, diff);
        ls += diff * diff;
    }
    double dl = (double)ls;
    #pragma unroll
    for (int off = 16; off; off >>= 1)
        dl += __shfl_xor_sync(0xffffffffu, dl, off);
    if ((threadIdx.x & 31) == 0) atomicAdd(&g_loss_acc, dl);
}

__global__ void vq_finalize_kernel(float* __restrict__ out_loss) {
    double mse = g_loss_acc / (double)TOTAL;
    float m = (float)mse;
    *out_loss = m + 0.25f * m;
}

// ---------------------------------------------------------------------------
extern "C" void kernel_launch(void* const* d_in, const int* in_sizes, int n_in,
                              void* d_out, int out_size) {
    const float* z  = (const float*)d_in[0];
    const float* cb = (const float*)d_in[1];
    float* out       = (float*)d_out;
    float* out_idx_f = out + TOTAL;
    float* out_loss  = out_idx_f + NROWS;

    cudaFuncSetAttribute(vq_mma_kernel,
                         cudaFuncAttributeMaxDynamicSharedMemorySize, GEMM_SMEM);
    cudaFuncSetAttribute(vq_rescue_kernel,
                         cudaFuncAttributeMaxDynamicSharedMemorySize, RS_SMEM);

    vq_init_kernel<<<1, 1>>>();
    vq_prep_cb_kernel<<<(KCB * DIMD) / 256, 256>>>(cb);
    vq_wsq_kernel<<<KCB / 256, 256>>>(cb);
    vq_prep_z_kernel<<<dim3(TT / 32, DIMD / 32, BBATCH), dim3(32, 8)>>>(z);
    vq_zsq_kernel<<<NROWS / 256, 256>>>(z);
    vq_mma_kernel<<<NROWS / 128, 256, GEMM_SMEM>>>(out_idx_f);
    vq_compact_kernel<<<NROWS / 256, 256>>>();
    vq_rescue_kernel<<<128, 256, RS_SMEM>>>(z, cb, out_idx_f);
    vq_gather_kernel<<<4096, 256>>>(z, cb, out);
    vq_finalize_kernel<<<1, 1>>>(out_loss);
}